// round 13
// baseline (speedup 1.0000x reference)
#include <cuda_runtime.h>
#include <cuda_bf16.h>
#include <cstdint>

// Problem dims
#define BBATCH 8
#define CTX    4096
#define QSTN   512
#define EDIM   300
#define HDIM   128

// Scratch (device globals: no allocation allowed in kernel_launch)
__device__ float g_ctx_logits[(size_t)BBATCH * CTX  * HDIM];   // 16 MB
__device__ float g_qst_logits[(size_t)BBATCH * QSTN * HDIM];   // 2 MB

// ---- tf32 mma helpers -----------------------------------------------------
__device__ __forceinline__ unsigned cvt_tf32(float f) {
    unsigned u; asm("cvt.rna.tf32.f32 %0, %1;" : "=r"(u) : "f"(f)); return u;
}
__device__ __forceinline__ float cvtf_tf32(float f) {
    return __uint_as_float(cvt_tf32(f));
}
// D(16x8,f32) += A(16x8,tf32,row) * B(8x8,tf32,col)
__device__ __forceinline__ void mma8(float& d0, float& d1, float& d2, float& d3,
                                     unsigned a0, unsigned a1, unsigned a2, unsigned a3,
                                     unsigned b0, unsigned b1) {
    asm volatile("mma.sync.aligned.m16n8k8.row.col.f32.tf32.tf32.f32 "
                 "{%0,%1,%2,%3}, {%4,%5,%6,%7}, {%8,%9}, {%0,%1,%2,%3};"
                 : "+f"(d0), "+f"(d1), "+f"(d2), "+f"(d3)
                 : "r"(a0), "r"(a1), "r"(a2), "r"(a3), "r"(b0), "r"(b1));
}

// ---------------------------------------------------------------------------
// Kernel 1: logits = ReLU(x @ W^T + b), 2xTF32 compensated (unchanged, ~42us)
// ---------------------------------------------------------------------------
#define KSP 20   // smem row stride: 20 mod 32 -> conflict-free frag loads

__global__ __launch_bounds__(256) void logits_mma(const float* __restrict__ ctx,
                                                  const float* __restrict__ qst,
                                                  const float* __restrict__ W,
                                                  const float* __restrict__ bias,
                                                  float* __restrict__ ctxL,
                                                  float* __restrict__ qstL) {
    __shared__ float xh[128 * KSP], xl[128 * KSP];
    __shared__ float wh[128 * KSP];
    __shared__ float bs[HDIM];

    const int tid  = threadIdx.x;
    const int warp = tid >> 5, lane = tid & 31;
    const int rl   = lane >> 2, cl = lane & 3;

    const bool is_ctx = (blockIdx.x < 256);
    const int  row0   = (is_ctx ? blockIdx.x : (blockIdx.x - 256)) * 128;
    const float* x    = is_ctx ? ctx  : qst;
    float*       out  = is_ctx ? ctxL : qstL;

    if (tid < HDIM) bs[tid] = bias[tid];

    float d[16][4];
#pragma unroll
    for (int t = 0; t < 16; t++)
#pragma unroll
        for (int i = 0; i < 4; i++) d[t][i] = 0.0f;

    for (int s = 0; s < 19; s++) {              // 19*16 = 304 >= 300
        const int k0 = s * 16;
        __syncthreads();
#pragma unroll
        for (int i = 0; i < 4; i++) {
            int f = tid + 256 * i;
            if (f < 512) {
                const int r  = f >> 2;
                const int c4 = (f & 3) << 2;
                const int ge = k0 + c4;
                float4 v = make_float4(0.f, 0.f, 0.f, 0.f);
                if (ge + 3 < EDIM) v = *(const float4*)(x + (size_t)(row0 + r) * EDIM + ge);
                float4 h4, l4;
                h4.x = cvtf_tf32(v.x); l4.x = cvtf_tf32(v.x - h4.x);
                h4.y = cvtf_tf32(v.y); l4.y = cvtf_tf32(v.y - h4.y);
                h4.z = cvtf_tf32(v.z); l4.z = cvtf_tf32(v.z - h4.z);
                h4.w = cvtf_tf32(v.w); l4.w = cvtf_tf32(v.w - h4.w);
                *(float4*)(xh + r * KSP + c4) = h4;
                *(float4*)(xl + r * KSP + c4) = l4;
            } else {
                f -= 512;
                const int r  = f >> 2;
                const int c4 = (f & 3) << 2;
                const int ge = k0 + c4;
                float4 v = make_float4(0.f, 0.f, 0.f, 0.f);
                if (ge + 3 < EDIM) v = *(const float4*)(W + (size_t)r * EDIM + ge);
                float4 h4;
                h4.x = cvtf_tf32(v.x);
                h4.y = cvtf_tf32(v.y);
                h4.z = cvtf_tf32(v.z);
                h4.w = cvtf_tf32(v.w);
                *(float4*)(wh + r * KSP + c4) = h4;
            }
        }
        __syncthreads();

#pragma unroll
        for (int kk = 0; kk < 16; kk += 8) {
            const int ab = (warp * 16 + rl) * KSP + kk + cl;
            unsigned ah0 = __float_as_uint(xh[ab]);
            unsigned ah1 = __float_as_uint(xh[ab + 8 * KSP]);
            unsigned ah2 = __float_as_uint(xh[ab + 4]);
            unsigned ah3 = __float_as_uint(xh[ab + 8 * KSP + 4]);
            unsigned al0 = __float_as_uint(xl[ab]);
            unsigned al1 = __float_as_uint(xl[ab + 8 * KSP]);
            unsigned al2 = __float_as_uint(xl[ab + 4]);
            unsigned al3 = __float_as_uint(xl[ab + 8 * KSP + 4]);
#pragma unroll
            for (int t = 0; t < 16; t++) {
                const int bi = (t * 8 + rl) * KSP + kk + cl;
                unsigned bh0 = __float_as_uint(wh[bi]), bh1 = __float_as_uint(wh[bi + 4]);
                mma8(d[t][0], d[t][1], d[t][2], d[t][3], ah0, ah1, ah2, ah3, bh0, bh1);
                mma8(d[t][0], d[t][1], d[t][2], d[t][3], al0, al1, al2, al3, bh0, bh1);
            }
        }
    }

    const int rlo = row0 + warp * 16 + rl;
    const int rhi = rlo + 8;
#pragma unroll
    for (int t = 0; t < 16; t++) {
        const int c0 = t * 8 + 2 * cl;
        const float b0 = bs[c0], b1 = bs[c0 + 1];
        float2 v0, v1;
        v0.x = cvtf_tf32(fmaxf(d[t][0] + b0, 0.0f));
        v0.y = cvtf_tf32(fmaxf(d[t][1] + b1, 0.0f));
        v1.x = cvtf_tf32(fmaxf(d[t][2] + b0, 0.0f));
        v1.y = cvtf_tf32(fmaxf(d[t][3] + b1, 0.0f));
        *(float2*)(out + (size_t)rlo * HDIM + c0) = v0;
        *(float2*)(out + (size_t)rhi * HDIM + c0) = v1;
    }
}

// ---------------------------------------------------------------------------
// Kernel 2: fused flash attention (R10 skeleton: 64 rows, 8 warps = 4 pairs,
// 2 CTAs/SM) + 8-column interleave permutation so every mma fragment pair
// (logical cols k, k+4) is one aligned LDS.64:
//   phys(k) = (k & ~7) | ((k & 3) << 1) | ((k >> 2) & 1)
// Strides 136/136/72 (== 8 mod 32) -> all LDS.64 frag loads conflict-free
// per half-warp; phase-2 V column loads conflict-free via permuted h.
// ---------------------------------------------------------------------------
#define CSP 136
#define QSP 136
#define PSP 72
// floats: cs 64*136=8704, qs 64*136=8704, ps 4*16*72=4608, red 256 -> 22272
#define ATTN_SMEM (22272 * 4 + QSTN * 4)   // 91136 B -> 2 CTAs/SM

__global__ __launch_bounds__(256, 2) void attn_mma(const float* __restrict__ ctxL,
                                                   const float* __restrict__ qstL,
                                                   const int*   __restrict__ mask,
                                                   float* __restrict__ out) {
    extern __shared__ float sm[];
    float* cs   = sm;                     // 64 x 136 (permuted cols)
    float* qs   = cs + 64 * CSP;          // 64 x 136 (permuted cols; Q and V view)
    float* ps   = qs + 64 * QSP;          // [4 pairs][16 rows][72] (permuted cols)
    float* redm = ps + 4 * 16 * PSP;      // [4][2][16] partial row max
    float* reds = redm + 128;             // [4][2][16] partial row sum
    int*   ms   = (int*)(reds + 128);     // 512

    const int tid  = threadIdx.x;
    const int warp = tid >> 5, lane = tid & 31;
    const int rl   = lane >> 2, cl = lane & 3;
    const int pair = warp >> 1, half = warp & 1;
    const int bb   = blockIdx.x >> 6;
    const int ct   = blockIdx.x & 63;
    const int row0 = ct * 64;
    const int r0   = pair * 16;
    float* pr = ps + pair * 16 * PSP;

    // permuted column offsets for this thread's P-store / A-frag roles
    const int pc0 = ((cl & 1) << 2) + (cl >> 1);        // perm8(2*cl)   in {0,4,1,5}
    const int pc1 = pc0 + 2;                            // perm8(2*cl+1) in {2,6,3,7}
    const int prl = ((rl & 3) << 1) | (rl >> 2);        // perm8(rl), rl<8

    const float* cbase = ctxL + ((size_t)bb * CTX + row0) * HDIM;
    const float* qbase = qstL + (size_t)bb * QSTN * HDIM;

    // fill cs with permuted columns: h=4j+i -> phys 8*(j>>1) + 2*i + (j&1)
    for (int f = tid; f < 2048; f += 256) {
        const int r = f >> 5, j = f & 31;
        float4 v = *(const float4*)(cbase + (size_t)r * HDIM + 4 * j);
        float* dst = cs + r * CSP + 8 * (j >> 1) + (j & 1);
        dst[0] = v.x; dst[2] = v.y; dst[4] = v.z; dst[6] = v.w;
    }
    for (int i = tid; i < QSTN; i += 256) ms[i] = mask[bb * QSTN + i];

    const float NEG_INF = __int_as_float(0xff800000);
    float o[8][4];
#pragma unroll
    for (int t = 0; t < 8; t++)
#pragma unroll
        for (int i = 0; i < 4; i++) o[t][i] = 0.0f;
    float m_lo = NEG_INF, m_hi = NEG_INF, l_lo = 0.0f, l_hi = 0.0f;

    for (int qc = 0; qc < QSTN / 64; qc++) {
        __syncthreads();               // previous chunk fully consumed (qs, ps, red)
        for (int f = tid; f < 2048; f += 256) {
            const int q = f >> 5, j = f & 31;
            float4 v = *(const float4*)(qbase + (size_t)qc * 64 * HDIM
                                        + (size_t)q * HDIM + 4 * j);
            float* dst = qs + q * QSP + 8 * (j >> 1) + (j & 1);
            dst[0] = v.x; dst[2] = v.y; dst[4] = v.z; dst[6] = v.w;
        }
        __syncthreads();

        // ---- phase 1: S[16 x 32] = C @ Q^T (this warp's q half) ----------
        float s[4][4];
#pragma unroll
        for (int t = 0; t < 4; t++)
#pragma unroll
            for (int i = 0; i < 4; i++) s[t][i] = 0.0f;

#pragma unroll
        for (int k0 = 0; k0 < HDIM; k0 += 8) {
            // A frags: (a0,a2) and (a1,a3) each one LDS.64
            float2 tA0 = *(const float2*)&cs[(r0 + rl) * CSP + k0 + 2 * cl];
            float2 tA1 = *(const float2*)&cs[(r0 + 8 + rl) * CSP + k0 + 2 * cl];
            unsigned a0 = __float_as_uint(tA0.x), a2 = __float_as_uint(tA0.y);
            unsigned a1 = __float_as_uint(tA1.x), a3 = __float_as_uint(tA1.y);
#pragma unroll
            for (int t = 0; t < 4; t++) {
                float2 tB = *(const float2*)&qs[(half * 32 + t * 8 + rl) * QSP + k0 + 2 * cl];
                mma8(s[t][0], s[t][1], s[t][2], s[t][3], a0, a1, a2, a3,
                     __float_as_uint(tB.x), __float_as_uint(tB.y));
            }
        }

        // ---- masked partial row max over this half -----------------------
        const int qb = qc * 64 + half * 32;
        float mx_lo = NEG_INF, mx_hi = NEG_INF;
#pragma unroll
        for (int t = 0; t < 4; t++) {
            const int c0 = t * 8 + 2 * cl;
            const int m0 = ms[qb + c0], m1 = ms[qb + c0 + 1];
            if (m0) { mx_lo = fmaxf(mx_lo, s[t][0]); mx_hi = fmaxf(mx_hi, s[t][2]); }
            if (m1) { mx_lo = fmaxf(mx_lo, s[t][1]); mx_hi = fmaxf(mx_hi, s[t][3]); }
        }
#pragma unroll
        for (int off = 1; off <= 2; off <<= 1) {
            mx_lo = fmaxf(mx_lo, __shfl_xor_sync(0xffffffffu, mx_lo, off));
            mx_hi = fmaxf(mx_hi, __shfl_xor_sync(0xffffffffu, mx_hi, off));
        }
        if (cl == 0) {
            redm[(pair * 2 + half) * 16 + rl]     = mx_lo;
            redm[(pair * 2 + half) * 16 + rl + 8] = mx_hi;
        }
        asm volatile("bar.sync %0, 64;" :: "r"(pair + 1) : "memory");
        mx_lo = fmaxf(mx_lo, redm[(pair * 2 + (1 - half)) * 16 + rl]);
        mx_hi = fmaxf(mx_hi, redm[(pair * 2 + (1 - half)) * 16 + rl + 8]);

        const float mn_lo = fmaxf(m_lo, mx_lo);
        const float mn_hi = fmaxf(m_hi, mx_hi);
        const float sc_lo = (m_lo == NEG_INF) ? 0.0f : __expf(m_lo - mn_lo);
        const float sc_hi = (m_hi == NEG_INF) ? 0.0f : __expf(m_hi - mn_hi);

        // ---- exp, P -> smem at PERMUTED cols, partial sums ---------------
        float sum_lo = 0.0f, sum_hi = 0.0f;
#pragma unroll
        for (int t = 0; t < 4; t++) {
            const int c0 = t * 8 + 2 * cl;
            const int m0 = ms[qb + c0], m1 = ms[qb + c0 + 1];
            float p0 = m0 ? cvtf_tf32(__expf(s[t][0] - mn_lo)) : 0.0f;
            float p1 = m1 ? cvtf_tf32(__expf(s[t][1] - mn_lo)) : 0.0f;
            float p2 = m0 ? cvtf_tf32(__expf(s[t][2] - mn_hi)) : 0.0f;
            float p3 = m1 ? cvtf_tf32(__expf(s[t][3] - mn_hi)) : 0.0f;
            sum_lo += p0 + p1;
            sum_hi += p2 + p3;
            const int colb = half * 32 + t * 8;
            pr[rl * PSP + colb + pc0]       = p0;
            pr[rl * PSP + colb + pc1]       = p1;
            pr[(rl + 8) * PSP + colb + pc0] = p2;
            pr[(rl + 8) * PSP + colb + pc1] = p3;
        }
#pragma unroll
        for (int off = 1; off <= 2; off <<= 1) {
            sum_lo += __shfl_xor_sync(0xffffffffu, sum_lo, off);
            sum_hi += __shfl_xor_sync(0xffffffffu, sum_hi, off);
        }
        if (cl == 0) {
            reds[(pair * 2 + half) * 16 + rl]     = sum_lo;
            reds[(pair * 2 + half) * 16 + rl + 8] = sum_hi;
        }
        asm volatile("bar.sync %0, 64;" :: "r"(pair + 1) : "memory");  // also orders ps
        sum_lo += reds[(pair * 2 + (1 - half)) * 16 + rl];
        sum_hi += reds[(pair * 2 + (1 - half)) * 16 + rl + 8];

        l_lo = l_lo * sc_lo + sum_lo;
        l_hi = l_hi * sc_hi + sum_hi;
        m_lo = mn_lo; m_hi = mn_hi;

#pragma unroll
        for (int t = 0; t < 8; t++) {
            o[t][0] *= sc_lo; o[t][1] *= sc_lo;
            o[t][2] *= sc_hi; o[t][3] *= sc_hi;
        }

        // ---- phase 2: O[16 x 64] += P @ V (this warp's h half) -----------
#pragma unroll
        for (int k0 = 0; k0 < 64; k0 += 8) {
            float2 tA0 = *(const float2*)&pr[rl * PSP + k0 + 2 * cl];
            float2 tA1 = *(const float2*)&pr[(8 + rl) * PSP + k0 + 2 * cl];
            unsigned a0 = __float_as_uint(tA0.x), a2 = __float_as_uint(tA0.y);
            unsigned a1 = __float_as_uint(tA1.x), a3 = __float_as_uint(tA1.y);
#pragma unroll
            for (int t = 0; t < 8; t++) {
                // V[q][h]: rows q = k0+cl, k0+cl+4; col h at permuted position
                const int hphys = half * 64 + t * 8 + prl;
                unsigned b0 = __float_as_uint(qs[(k0 + cl) * QSP + hphys]);
                unsigned b1 = __float_as_uint(qs[(k0 + cl + 4) * QSP + hphys]);
                mma8(o[t][0], o[t][1], o[t][2], o[t][3], a0, a1, a2, a3, b0, b1);
            }
        }
    }

    // ---- epilogue: normalize + store (logical cols) ----------------------
    const float inv_lo = 1.0f / l_lo;
    const float inv_hi = 1.0f / l_hi;
    float* ob = out + ((size_t)bb * CTX + row0) * HDIM;
    const int rlo = r0 + rl, rhi = rlo + 8;
#pragma unroll
    for (int t = 0; t < 8; t++) {
        const int c0 = half * 64 + t * 8 + 2 * cl;
        *(float2*)(ob + (size_t)rlo * HDIM + c0) =
            make_float2(o[t][0] * inv_lo, o[t][1] * inv_lo);
        *(float2*)(ob + (size_t)rhi * HDIM + c0) =
            make_float2(o[t][2] * inv_hi, o[t][3] * inv_hi);
    }
}

// ---------------------------------------------------------------------------
extern "C" void kernel_launch(void* const* d_in, const int* in_sizes, int n_in,
                              void* d_out, int out_size) {
    const float* ctx  = (const float*)d_in[0];   // [8,4096,300]
    const float* qst  = (const float*)d_in[1];   // [8,512,300]
    const int*   mask = (const int*)d_in[2];     // [8,512]
    const float* W    = (const float*)d_in[3];   // [128,300]
    const float* bias = (const float*)d_in[4];   // [128]
    float*       out  = (float*)d_out;           // [8,4096,128]

    cudaFuncSetAttribute(attn_mma, cudaFuncAttributeMaxDynamicSharedMemorySize, ATTN_SMEM);

    void* p_ctxL = nullptr; void* p_qstL = nullptr;
    cudaGetSymbolAddress(&p_ctxL, g_ctx_logits);
    cudaGetSymbolAddress(&p_qstL, g_qst_logits);
    float* ctxL = (float*)p_ctxL;
    float* qstL = (float*)p_qstL;

    // fused logits: blocks [0,256) ctx rows, [256,288) qst rows
    logits_mma<<<288, 256>>>(ctx, qst, W, bias, ctxL, qstL);

    // fused scores -> online softmax -> AV (64 ctx rows, 8 warps per block)
    attn_mma<<<BBATCH * (CTX / 64), 256, ATTN_SMEM>>>(ctxL, qstL, mask, out);
}

// round 15
// speedup vs baseline: 1.0674x; 1.0674x over previous
#include <cuda_runtime.h>
#include <cuda_bf16.h>
#include <cstdint>

// Problem dims
#define BBATCH 8
#define CTX    4096
#define QSTN   512
#define EDIM   300
#define HDIM   128

// Scratch (device globals: no allocation allowed in kernel_launch)
__device__ float g_ctx_logits[(size_t)BBATCH * CTX  * HDIM];   // 16 MB
__device__ float g_qst_logits[(size_t)BBATCH * QSTN * HDIM];   // 2 MB

// ---- tf32 mma helpers (logits kernel) -------------------------------------
__device__ __forceinline__ unsigned cvt_tf32(float f) {
    unsigned u; asm("cvt.rna.tf32.f32 %0, %1;" : "=r"(u) : "f"(f)); return u;
}
__device__ __forceinline__ float cvtf_tf32(float f) {
    return __uint_as_float(cvt_tf32(f));
}
__device__ __forceinline__ void mma8(float& d0, float& d1, float& d2, float& d3,
                                     unsigned a0, unsigned a1, unsigned a2, unsigned a3,
                                     unsigned b0, unsigned b1) {
    asm volatile("mma.sync.aligned.m16n8k8.row.col.f32.tf32.tf32.f32 "
                 "{%0,%1,%2,%3}, {%4,%5,%6,%7}, {%8,%9}, {%0,%1,%2,%3};"
                 : "+f"(d0), "+f"(d1), "+f"(d2), "+f"(d3)
                 : "r"(a0), "r"(a1), "r"(a2), "r"(a3), "r"(b0), "r"(b1));
}

// ---- bf16 mma + ldmatrix helpers (attn kernel) -----------------------------
__device__ __forceinline__ void mmabf(float& d0, float& d1, float& d2, float& d3,
                                      unsigned a0, unsigned a1, unsigned a2, unsigned a3,
                                      unsigned b0, unsigned b1) {
    asm volatile("mma.sync.aligned.m16n8k16.row.col.f32.bf16.bf16.f32 "
                 "{%0,%1,%2,%3}, {%4,%5,%6,%7}, {%8,%9}, {%0,%1,%2,%3};"
                 : "+f"(d0), "+f"(d1), "+f"(d2), "+f"(d3)
                 : "r"(a0), "r"(a1), "r"(a2), "r"(a3), "r"(b0), "r"(b1));
}
__device__ __forceinline__ void ldsm_x4(unsigned& r0, unsigned& r1, unsigned& r2,
                                        unsigned& r3, unsigned addr) {
    asm volatile("ldmatrix.sync.aligned.m8n8.x4.shared.b16 {%0,%1,%2,%3}, [%4];"
                 : "=r"(r0), "=r"(r1), "=r"(r2), "=r"(r3) : "r"(addr));
}
__device__ __forceinline__ void ldsm_x2(unsigned& r0, unsigned& r1, unsigned addr) {
    asm volatile("ldmatrix.sync.aligned.m8n8.x2.shared.b16 {%0,%1}, [%2];"
                 : "=r"(r0), "=r"(r1) : "r"(addr));
}
__device__ __forceinline__ void ldsm_x2t(unsigned& r0, unsigned& r1, unsigned addr) {
    asm volatile("ldmatrix.sync.aligned.m8n8.x2.trans.shared.b16 {%0,%1}, [%2];"
                 : "=r"(r0), "=r"(r1) : "r"(addr));
}
// pack two f32 -> bf16x2; 'lo' goes to the low 16 bits (lower address / even col)
__device__ __forceinline__ unsigned pack_bf2(float lo, float hi) {
    unsigned r; asm("cvt.rn.bf16x2.f32 %0, %1, %2;" : "=r"(r) : "f"(hi), "f"(lo));
    return r;
}
__device__ __forceinline__ float bflo(unsigned u) { return __uint_as_float(u << 16); }
__device__ __forceinline__ float bfhi(unsigned u) { return __uint_as_float(u & 0xffff0000u); }

// ---------------------------------------------------------------------------
// Kernel 1: logits = ReLU(x @ W^T + b), 2xTF32 compensated (unchanged, ~42us)
// ---------------------------------------------------------------------------
#define KSP 20   // smem row stride: 20 mod 32 -> conflict-free frag loads

__global__ __launch_bounds__(256) void logits_mma(const float* __restrict__ ctx,
                                                  const float* __restrict__ qst,
                                                  const float* __restrict__ W,
                                                  const float* __restrict__ bias,
                                                  float* __restrict__ ctxL,
                                                  float* __restrict__ qstL) {
    __shared__ float xh[128 * KSP], xl[128 * KSP];
    __shared__ float wh[128 * KSP];
    __shared__ float bs[HDIM];

    const int tid  = threadIdx.x;
    const int warp = tid >> 5, lane = tid & 31;
    const int rl   = lane >> 2, cl = lane & 3;

    const bool is_ctx = (blockIdx.x < 256);
    const int  row0   = (is_ctx ? blockIdx.x : (blockIdx.x - 256)) * 128;
    const float* x    = is_ctx ? ctx  : qst;
    float*       out  = is_ctx ? ctxL : qstL;

    if (tid < HDIM) bs[tid] = bias[tid];

    float d[16][4];
#pragma unroll
    for (int t = 0; t < 16; t++)
#pragma unroll
        for (int i = 0; i < 4; i++) d[t][i] = 0.0f;

    for (int s = 0; s < 19; s++) {              // 19*16 = 304 >= 300
        const int k0 = s * 16;
        __syncthreads();
#pragma unroll
        for (int i = 0; i < 4; i++) {
            int f = tid + 256 * i;
            if (f < 512) {
                const int r  = f >> 2;
                const int c4 = (f & 3) << 2;
                const int ge = k0 + c4;
                float4 v = make_float4(0.f, 0.f, 0.f, 0.f);
                if (ge + 3 < EDIM) v = *(const float4*)(x + (size_t)(row0 + r) * EDIM + ge);
                float4 h4, l4;
                h4.x = cvtf_tf32(v.x); l4.x = cvtf_tf32(v.x - h4.x);
                h4.y = cvtf_tf32(v.y); l4.y = cvtf_tf32(v.y - h4.y);
                h4.z = cvtf_tf32(v.z); l4.z = cvtf_tf32(v.z - h4.z);
                h4.w = cvtf_tf32(v.w); l4.w = cvtf_tf32(v.w - h4.w);
                *(float4*)(xh + r * KSP + c4) = h4;
                *(float4*)(xl + r * KSP + c4) = l4;
            } else {
                f -= 512;
                const int r  = f >> 2;
                const int c4 = (f & 3) << 2;
                const int ge = k0 + c4;
                float4 v = make_float4(0.f, 0.f, 0.f, 0.f);
                if (ge + 3 < EDIM) v = *(const float4*)(W + (size_t)r * EDIM + ge);
                float4 h4;
                h4.x = cvtf_tf32(v.x);
                h4.y = cvtf_tf32(v.y);
                h4.z = cvtf_tf32(v.z);
                h4.w = cvtf_tf32(v.w);
                *(float4*)(wh + r * KSP + c4) = h4;
            }
        }
        __syncthreads();

#pragma unroll
        for (int kk = 0; kk < 16; kk += 8) {
            const int ab = (warp * 16 + rl) * KSP + kk + cl;
            unsigned ah0 = __float_as_uint(xh[ab]);
            unsigned ah1 = __float_as_uint(xh[ab + 8 * KSP]);
            unsigned ah2 = __float_as_uint(xh[ab + 4]);
            unsigned ah3 = __float_as_uint(xh[ab + 8 * KSP + 4]);
            unsigned al0 = __float_as_uint(xl[ab]);
            unsigned al1 = __float_as_uint(xl[ab + 8 * KSP]);
            unsigned al2 = __float_as_uint(xl[ab + 4]);
            unsigned al3 = __float_as_uint(xl[ab + 8 * KSP + 4]);
#pragma unroll
            for (int t = 0; t < 16; t++) {
                const int bi = (t * 8 + rl) * KSP + kk + cl;
                unsigned bh0 = __float_as_uint(wh[bi]), bh1 = __float_as_uint(wh[bi + 4]);
                mma8(d[t][0], d[t][1], d[t][2], d[t][3], ah0, ah1, ah2, ah3, bh0, bh1);
                mma8(d[t][0], d[t][1], d[t][2], d[t][3], al0, al1, al2, al3, bh0, bh1);
            }
        }
    }

    const int rlo = row0 + warp * 16 + rl;
    const int rhi = rlo + 8;
#pragma unroll
    for (int t = 0; t < 16; t++) {
        const int c0 = t * 8 + 2 * cl;
        const float b0 = bs[c0], b1 = bs[c0 + 1];
        float2 v0, v1;
        v0.x = cvtf_tf32(fmaxf(d[t][0] + b0, 0.0f));
        v0.y = cvtf_tf32(fmaxf(d[t][1] + b1, 0.0f));
        v1.x = cvtf_tf32(fmaxf(d[t][2] + b0, 0.0f));
        v1.y = cvtf_tf32(fmaxf(d[t][3] + b1, 0.0f));
        *(float2*)(out + (size_t)rlo * HDIM + c0) = v0;
        *(float2*)(out + (size_t)rhi * HDIM + c0) = v1;
    }
}

// ---------------------------------------------------------------------------
// Kernel 2: fused flash attention, bf16 hi/lo 3-term mma + ldmatrix.
// R10 skeleton: 64 ctx rows, 8 warps = 4 pairs, 2 CTAs/SM. Pair owns 16 rows;
// phase1 splits the 64-q chunk (32 q/warp), phase2 splits h (64/warp).
// Tiles stored as bf16 hi+lo: x = hi + lo exactly (logits are tf32-grid),
// products via 3 mma terms (hi*hi + hi*lo + lo*hi), error ~2^-16.
// Row strides: 136 bf16 (272 B = 17x16B) and 72 bf16 (144 B = 9x16B) ->
// all ldmatrix phases hit 8 distinct 16B bank-groups (conflict-free).
// ---------------------------------------------------------------------------
#define CSP2 136
#define QSP2 136
#define PSP2 72
// byte offsets inside dynamic smem
#define CS_H 0
#define CS_L 17408
#define QS_H 34816
#define QS_L 52224
#define PS_H 69632
#define PS_L 78848
#define REDM 88064
#define REDS 88576
#define MS_O 89088
#define ATTN_SMEM 91136   // -> 2 CTAs/SM

__global__ __launch_bounds__(256, 2) void attn_mma(const float* __restrict__ ctxL,
                                                   const float* __restrict__ qstL,
                                                   const int*   __restrict__ mask,
                                                   float* __restrict__ out) {
    extern __shared__ char smb[];
    const unsigned sbase = (unsigned)__cvta_generic_to_shared(smb);
    float* redm = (float*)(smb + REDM);
    float* reds = (float*)(smb + REDS);
    int*   ms   = (int*)(smb + MS_O);

    const int tid  = threadIdx.x;
    const int warp = tid >> 5, lane = tid & 31;
    const int rl   = lane >> 2, cl = lane & 3;
    const int pair = warp >> 1, half = warp & 1;
    const int bb   = blockIdx.x >> 6;
    const int ct   = blockIdx.x & 63;
    const int row0 = ct * 64;
    const int r0   = pair * 16;

    const float* cbase = ctxL + ((size_t)bb * CTX + row0) * HDIM;
    const float* qbase = qstL + (size_t)bb * QSTN * HDIM;

    // ---- fill cs (hi/lo bf16 split), mask ----
    for (int f = tid; f < 2048; f += 256) {
        const int r = f >> 5, c4 = (f & 31) << 2;
        float4 v = *(const float4*)(cbase + (size_t)r * HDIM + c4);
        unsigned h01 = pack_bf2(v.x, v.y), h23 = pack_bf2(v.z, v.w);
        unsigned l01 = pack_bf2(v.x - bflo(h01), v.y - bfhi(h01));
        unsigned l23 = pack_bf2(v.z - bflo(h23), v.w - bfhi(h23));
        const int bo = r * (CSP2 * 2) + c4 * 2;
        *(uint2*)(smb + CS_H + bo) = make_uint2(h01, h23);
        *(uint2*)(smb + CS_L + bo) = make_uint2(l01, l23);
    }
    for (int i = tid; i < QSTN; i += 256) ms[i] = mask[bb * QSTN + i];

    // ---- hoisted ldmatrix lane addresses (byte offsets) ----
    // phase1 A (cs, x4): rows r0+(lane&15), k-chunk +8 for lanes>=16
    const unsigned aoffB = ((unsigned)(r0 + (lane & 15)) * CSP2 + ((lane >> 4) << 3)) * 2;
    // phase1 B (qs, x2): rows half*32+(lane&7) [+t*8], k-chunk +8 for lanes 8-15
    const unsigned boffB = ((unsigned)(half * 32 + (lane & 7)) * QSP2 + (((lane >> 3) & 1) << 3)) * 2;
    // phase2 A (ps, x4): rows (lane&15), q-chunk +8 for lanes>=16
    const unsigned poffB = ((unsigned)(lane & 15) * PSP2 + ((lane >> 4) << 3)) * 2;
    // phase2 B (qs as V, x2.trans): rows q0+(lane&15), col h_t
    const unsigned voffB = ((unsigned)(lane & 15) * QSP2) * 2;
    const unsigned prbase = (unsigned)pair * 16 * PSP2 * 2;   // pair's ps block (bytes)

    const float NEG_INF = __int_as_float(0xff800000);
    float o[8][4];
#pragma unroll
    for (int t = 0; t < 8; t++)
#pragma unroll
        for (int i = 0; i < 4; i++) o[t][i] = 0.0f;
    float m_lo = NEG_INF, m_hi = NEG_INF, l_lo = 0.0f, l_hi = 0.0f;

    for (int qc = 0; qc < QSTN / 64; qc++) {
        __syncthreads();               // previous chunk fully consumed (qs, ps, red)
        for (int f = tid; f < 2048; f += 256) {
            const int q = f >> 5, c4 = (f & 31) << 2;
            float4 v = *(const float4*)(qbase + (size_t)qc * 64 * HDIM
                                        + (size_t)q * HDIM + c4);
            unsigned h01 = pack_bf2(v.x, v.y), h23 = pack_bf2(v.z, v.w);
            unsigned l01 = pack_bf2(v.x - bflo(h01), v.y - bfhi(h01));
            unsigned l23 = pack_bf2(v.z - bflo(h23), v.w - bfhi(h23));
            const int bo = q * (QSP2 * 2) + c4 * 2;
            *(uint2*)(smb + QS_H + bo) = make_uint2(h01, h23);
            *(uint2*)(smb + QS_L + bo) = make_uint2(l01, l23);
        }
        __syncthreads();

        // ---- phase 1: S[16 x 32] = C @ Q^T (this warp's q half) ----------
        float s[4][4];
#pragma unroll
        for (int t = 0; t < 4; t++)
#pragma unroll
            for (int i = 0; i < 4; i++) s[t][i] = 0.0f;

#pragma unroll
        for (int k0 = 0; k0 < HDIM; k0 += 16) {
            unsigned ah0, ah1, ah2, ah3, al0, al1, al2, al3;
            ldsm_x4(ah0, ah1, ah2, ah3, sbase + CS_H + aoffB + k0 * 2);
            ldsm_x4(al0, al1, al2, al3, sbase + CS_L + aoffB + k0 * 2);
#pragma unroll
            for (int t = 0; t < 4; t++) {
                const unsigned qa = boffB + ((unsigned)(t * 8) * QSP2 + k0) * 2;
                unsigned qh0, qh1, ql0, ql1;
                ldsm_x2(qh0, qh1, sbase + QS_H + qa);
                ldsm_x2(ql0, ql1, sbase + QS_L + qa);
                mmabf(s[t][0], s[t][1], s[t][2], s[t][3], ah0, ah1, ah2, ah3, qh0, qh1);
                mmabf(s[t][0], s[t][1], s[t][2], s[t][3], ah0, ah1, ah2, ah3, ql0, ql1);
                mmabf(s[t][0], s[t][1], s[t][2], s[t][3], al0, al1, al2, al3, qh0, qh1);
            }
        }

        // ---- masked partial row max over this half -----------------------
        const int qb = qc * 64 + half * 32;
        float mx_lo = NEG_INF, mx_hi = NEG_INF;
#pragma unroll
        for (int t = 0; t < 4; t++) {
            const int c0 = t * 8 + 2 * cl;
            const int m0 = ms[qb + c0], m1 = ms[qb + c0 + 1];
            if (m0) { mx_lo = fmaxf(mx_lo, s[t][0]); mx_hi = fmaxf(mx_hi, s[t][2]); }
            if (m1) { mx_lo = fmaxf(mx_lo, s[t][1]); mx_hi = fmaxf(mx_hi, s[t][3]); }
        }
#pragma unroll
        for (int off = 1; off <= 2; off <<= 1) {
            mx_lo = fmaxf(mx_lo, __shfl_xor_sync(0xffffffffu, mx_lo, off));
            mx_hi = fmaxf(mx_hi, __shfl_xor_sync(0xffffffffu, mx_hi, off));
        }
        if (cl == 0) {
            redm[(pair * 2 + half) * 16 + rl]     = mx_lo;
            redm[(pair * 2 + half) * 16 + rl + 8] = mx_hi;
        }
        asm volatile("bar.sync %0, 64;" :: "r"(pair + 1) : "memory");
        mx_lo = fmaxf(mx_lo, redm[(pair * 2 + (1 - half)) * 16 + rl]);
        mx_hi = fmaxf(mx_hi, redm[(pair * 2 + (1 - half)) * 16 + rl + 8]);

        const float mn_lo = fmaxf(m_lo, mx_lo);
        const float mn_hi = fmaxf(m_hi, mx_hi);
        const float sc_lo = (m_lo == NEG_INF) ? 0.0f : __expf(m_lo - mn_lo);
        const float sc_hi = (m_hi == NEG_INF) ? 0.0f : __expf(m_hi - mn_hi);

        // ---- exp, P -> smem as bf16 hi/lo, partial sums ------------------
        float sum_lo = 0.0f, sum_hi = 0.0f;
#pragma unroll
        for (int t = 0; t < 4; t++) {
            const int c0 = t * 8 + 2 * cl;
            const int m0 = ms[qb + c0], m1 = ms[qb + c0 + 1];
            float p0 = m0 ? __expf(s[t][0] - mn_lo) : 0.0f;
            float p1 = m1 ? __expf(s[t][1] - mn_lo) : 0.0f;
            float p2 = m0 ? __expf(s[t][2] - mn_hi) : 0.0f;
            float p3 = m1 ? __expf(s[t][3] - mn_hi) : 0.0f;
            const int colB = (half * 32 + c0) * 2;   // byte offset of col c0
            unsigned h01 = pack_bf2(p0, p1);
            unsigned l01 = pack_bf2(p0 - bflo(h01), p1 - bfhi(h01));
            unsigned h23 = pack_bf2(p2, p3);
            unsigned l23 = pack_bf2(p2 - bflo(h23), p3 - bfhi(h23));
            // sums use the representable (hi+lo) values implicitly = exact p
            sum_lo += p0 + p1;
            sum_hi += p2 + p3;
            *(unsigned*)(smb + PS_H + prbase + rl * (PSP2 * 2) + colB)       = h01;
            *(unsigned*)(smb + PS_L + prbase + rl * (PSP2 * 2) + colB)       = l01;
            *(unsigned*)(smb + PS_H + prbase + (rl + 8) * (PSP2 * 2) + colB) = h23;
            *(unsigned*)(smb + PS_L + prbase + (rl + 8) * (PSP2 * 2) + colB) = l23;
        }
#pragma unroll
        for (int off = 1; off <= 2; off <<= 1) {
            sum_lo += __shfl_xor_sync(0xffffffffu, sum_lo, off);
            sum_hi += __shfl_xor_sync(0xffffffffu, sum_hi, off);
        }
        if (cl == 0) {
            reds[(pair * 2 + half) * 16 + rl]     = sum_lo;
            reds[(pair * 2 + half) * 16 + rl + 8] = sum_hi;
        }
        asm volatile("bar.sync %0, 64;" :: "r"(pair + 1) : "memory");  // also orders ps
        sum_lo += reds[(pair * 2 + (1 - half)) * 16 + rl];
        sum_hi += reds[(pair * 2 + (1 - half)) * 16 + rl + 8];

        l_lo = l_lo * sc_lo + sum_lo;
        l_hi = l_hi * sc_hi + sum_hi;
        m_lo = mn_lo; m_hi = mn_hi;

#pragma unroll
        for (int t = 0; t < 8; t++) {
            o[t][0] *= sc_lo; o[t][1] *= sc_lo;
            o[t][2] *= sc_hi; o[t][3] *= sc_hi;
        }

        // ---- phase 2: O[16 x 64] += P @ V (this warp's h half) -----------
#pragma unroll
        for (int q0 = 0; q0 < 64; q0 += 16) {
            unsigned ph0, ph1, ph2, ph3, pl0, pl1, pl2, pl3;
            ldsm_x4(ph0, ph1, ph2, ph3, sbase + PS_H + prbase + poffB + q0 * 2);
            ldsm_x4(pl0, pl1, pl2, pl3, sbase + PS_L + prbase + poffB + q0 * 2);
#pragma unroll
            for (int t = 0; t < 8; t++) {
                const int ht = half * 64 + t * 8;
                const unsigned va = voffB + ((unsigned)q0 * QSP2 + ht) * 2;
                unsigned vh0, vh1, vl0, vl1;
                ldsm_x2t(vh0, vh1, sbase + QS_H + va);
                ldsm_x2t(vl0, vl1, sbase + QS_L + va);
                mmabf(o[t][0], o[t][1], o[t][2], o[t][3], ph0, ph1, ph2, ph3, vh0, vh1);
                mmabf(o[t][0], o[t][1], o[t][2], o[t][3], ph0, ph1, ph2, ph3, vl0, vl1);
                mmabf(o[t][0], o[t][1], o[t][2], o[t][3], pl0, pl1, pl2, pl3, vh0, vh1);
            }
        }
    }

    // ---- epilogue: normalize + store -------------------------------------
    const float inv_lo = 1.0f / l_lo;
    const float inv_hi = 1.0f / l_hi;
    float* ob = out + ((size_t)bb * CTX + row0) * HDIM;
    const int rlo = r0 + rl, rhi = rlo + 8;
#pragma unroll
    for (int t = 0; t < 8; t++) {
        const int c0 = half * 64 + t * 8 + 2 * cl;
        *(float2*)(ob + (size_t)rlo * HDIM + c0) =
            make_float2(o[t][0] * inv_lo, o[t][1] * inv_lo);
        *(float2*)(ob + (size_t)rhi * HDIM + c0) =
            make_float2(o[t][2] * inv_hi, o[t][3] * inv_hi);
    }
}

// ---------------------------------------------------------------------------
extern "C" void kernel_launch(void* const* d_in, const int* in_sizes, int n_in,
                              void* d_out, int out_size) {
    const float* ctx  = (const float*)d_in[0];   // [8,4096,300]
    const float* qst  = (const float*)d_in[1];   // [8,512,300]
    const int*   mask = (const int*)d_in[2];     // [8,512]
    const float* W    = (const float*)d_in[3];   // [128,300]
    const float* bias = (const float*)d_in[4];   // [128]
    float*       out  = (float*)d_out;           // [8,4096,128]

    cudaFuncSetAttribute(attn_mma, cudaFuncAttributeMaxDynamicSharedMemorySize, ATTN_SMEM);

    void* p_ctxL = nullptr; void* p_qstL = nullptr;
    cudaGetSymbolAddress(&p_ctxL, g_ctx_logits);
    cudaGetSymbolAddress(&p_qstL, g_qst_logits);
    float* ctxL = (float*)p_ctxL;
    float* qstL = (float*)p_qstL;

    // fused logits: blocks [0,256) ctx rows, [256,288) qst rows
    logits_mma<<<288, 256>>>(ctx, qst, W, bias, ctxL, qstL);

    // fused scores -> online softmax -> AV (64 ctx rows, 8 warps per block)
    attn_mma<<<BBATCH * (CTX / 64), 256, ATTN_SMEM>>>(ctxL, qstL, mask, out);
}